// round 5
// baseline (speedup 1.0000x reference)
#include <cuda_runtime.h>
#include <math.h>

// VolatilityLoss: mean((std3(pred) - std3(targ))^2), sliding window w=3.
// B=512, S=8192, L=8190 outputs/row.
// Latency-bound kernel -> maximize occupancy: 4 outputs/thread, ~28 regs,
// one group per thread (4096x256 = exact cover), fused last-block finalize.

#define B_ROWS 512
#define S_LEN  8192
#define L_OUT  (S_LEN - 2)          // 8190
#define NBLOCKS 4096
#define NTHREADS 256
// NBLOCKS*NTHREADS*4 == B_ROWS*S_LEN exactly

__device__ float        g_partials[NBLOCKS];
__device__ unsigned int g_counter = 0;   // monotone across graph replays

__device__ __forceinline__ float sqrt_approx(float x) {
    float r;
    asm("sqrt.approx.f32 %0, %1;" : "=f"(r) : "f"(x));
    return r;
}

__device__ __forceinline__ float std3(float a, float b, float c) {
    float m  = (a + b + c) * (1.0f / 3.0f);
    float da = a - m, db = b - m, dc = c - m;
    float var = fmaf(da, da, fmaf(db, db, dc * dc)) * 0.5f;
    return sqrt_approx(var);   // var >= 0 by construction
}

#define WIN(pa, pb, pc, ta, tb, tc)                         \
    do {                                                    \
        float _d = std3(pa, pb, pc) - std3(ta, tb, tc);     \
        acc = fmaf(_d, _d, acc);                            \
    } while (0)

__global__ void __launch_bounds__(NTHREADS)
vol_loss_fused(const float* __restrict__ pred, const float* __restrict__ targ,
               float* __restrict__ out) {
    int g     = blockIdx.x * NTHREADS + threadIdx.x;
    int row   = g >> 11;             // 2048 groups per row
    int start = (g & 2047) << 2;     // 4 outputs starting here

    const float* pbase = pred + (size_t)row * S_LEN + start;
    const float* tbase = targ + (size_t)row * S_LEN + start;

    // Elements start..start+5 feed windows start..start+3.
    // Last group of a row (start=8188): float2 would cross the row and only
    // windows start,start+1 are valid — one predicate covers both.
    bool tail_ok = (start + 6) <= S_LEN;

    float4 p0 = ((const float4*)pbase)[0];
    float4 t0 = ((const float4*)tbase)[0];
    float2 p1 = make_float2(0.f, 0.f), t1 = make_float2(0.f, 0.f);
    if (tail_ok) {
        p1 = ((const float2*)(pbase + 4))[0];
        t1 = ((const float2*)(tbase + 4))[0];
    }

    float acc = 0.0f;
    WIN(p0.x, p0.y, p0.z,  t0.x, t0.y, t0.z);
    WIN(p0.y, p0.z, p0.w,  t0.y, t0.z, t0.w);
    if (tail_ok) {
        WIN(p0.z, p0.w, p1.x,  t0.z, t0.w, t1.x);
        WIN(p0.w, p1.x, p1.y,  t0.w, t1.x, t1.y);
    }

    // Deterministic intra-block reduction.
    #pragma unroll
    for (int o = 16; o > 0; o >>= 1)
        acc += __shfl_down_sync(0xffffffffu, acc, o);

    __shared__ float red[NTHREADS / 32];
    int lane = threadIdx.x & 31;
    int warp = threadIdx.x >> 5;
    if (lane == 0) red[warp] = acc;
    __syncthreads();

    __shared__ bool is_last;
    if (threadIdx.x == 0) {
        float v = 0.0f;
        #pragma unroll
        for (int w = 0; w < NTHREADS / 32; ++w) v += red[w];
        g_partials[blockIdx.x] = v;
        __threadfence();
        unsigned int old = atomicAdd(&g_counter, 1u);
        is_last = ((old + 1u) % (unsigned)NBLOCKS) == 0u;
    }
    __syncthreads();

    if (!is_last) return;

    // Last-arriving block: deterministic final reduction over 4096 partials.
    __shared__ double sh[NTHREADS];
    double s = 0.0;
    for (int i = threadIdx.x; i < NBLOCKS; i += NTHREADS)
        s += (double)g_partials[i];
    sh[threadIdx.x] = s;
    __syncthreads();
    #pragma unroll
    for (int stride = NTHREADS / 2; stride > 0; stride >>= 1) {
        if (threadIdx.x < stride) sh[threadIdx.x] += sh[threadIdx.x + stride];
        __syncthreads();
    }
    if (threadIdx.x == 0)
        out[0] = (float)(sh[0] / ((double)B_ROWS * (double)L_OUT));
}

extern "C" void kernel_launch(void* const* d_in, const int* in_sizes, int n_in,
                              void* d_out, int out_size) {
    const float* pred = (const float*)d_in[0];
    const float* targ = (const float*)d_in[1];
    vol_loss_fused<<<NBLOCKS, NTHREADS>>>(pred, targ, (float*)d_out);
}

// round 6
// speedup vs baseline: 1.4320x; 1.4320x over previous
#include <cuda_runtime.h>
#include <math.h>

// VolatilityLoss: mean((std3(pred) - std3(targ))^2), window w=3.
// B=512, S=8192, L=8190 outputs/row.
// Persistent 2-iter threads, 8 outputs/iter, shuffle-shared boundary elements,
// single-MUFU window pair: (sp-st)^2 = vp+vt-2*sqrt(vp*vt).

#define B_ROWS 512
#define S_LEN  8192
#define L_OUT  (S_LEN - 2)            // 8190
#define NBLOCKS 1024
#define NTHREADS 256
#define NITER 2
#define THREADS_TOTAL (NBLOCKS * NTHREADS)   // 262144; *NITER*8 == 512*8192

__device__ float        g_partials[NBLOCKS];
__device__ unsigned int g_counter = 0;   // monotone across graph replays

__device__ __forceinline__ float sqrt_approx(float x) {
    float r;
    asm("sqrt.approx.f32 %0, %1;" : "=f"(r) : "f"(x));
    return r;
}

// (std3(a,b,c) - std3(x,y,z))^2 with one sqrt:
// var = 0.5*q - s*s/6  (unbiased, w=3);  (sqrt(vp)-sqrt(vt))^2 = vp+vt-2*sqrt(vp*vt)
__device__ __forceinline__ float wpair(float a, float b, float c,
                                       float x, float y, float z) {
    float sp = a + b + c;
    float qp = fmaf(a, a, fmaf(b, b, c * c));
    float vp = fmaxf(fmaf(sp, sp * (-1.0f / 6.0f), 0.5f * qp), 0.0f);
    float st = x + y + z;
    float qt = fmaf(x, x, fmaf(y, y, z * z));
    float vt = fmaxf(fmaf(st, st * (-1.0f / 6.0f), 0.5f * qt), 0.0f);
    return (vp + vt) - 2.0f * sqrt_approx(vp * vt);
}

__global__ void __launch_bounds__(NTHREADS)
vol_loss_fused(const float* __restrict__ pred, const float* __restrict__ targ,
               float* __restrict__ out) {
    const int tid  = blockIdx.x * NTHREADS + threadIdx.x;
    const int lane = threadIdx.x & 31;
    float acc = 0.0f;

    #pragma unroll
    for (int it = 0; it < NITER; ++it) {
        int g     = tid + it * THREADS_TOTAL;
        int row   = g >> 10;             // 1024 8-elem groups per row
        int start = (g & 1023) << 3;

        const float* pb = pred + ((size_t)row << 13) + start;
        const float* tb = targ + ((size_t)row << 13) + start;

        float4 p0 = ((const float4*)pb)[0];
        float4 p1 = ((const float4*)pb)[1];
        float4 t0 = ((const float4*)tb)[0];
        float4 t1 = ((const float4*)tb)[1];

        // Elements start+8, start+9 live in lane+1's chunk (adjacent lanes own
        // adjacent chunks within a row). Row boundary (start=8184) always falls
        // on lane 31, which instead does a predicated float2 load.
        bool full = (start + 8) < S_LEN;     // false only at row end (lane 31)
        float px8 = __shfl_down_sync(0xffffffffu, p0.x, 1);
        float px9 = __shfl_down_sync(0xffffffffu, p0.y, 1);
        float tx8 = __shfl_down_sync(0xffffffffu, t0.x, 1);
        float tx9 = __shfl_down_sync(0xffffffffu, t0.y, 1);
        if (lane == 31) {
            px8 = px9 = tx8 = tx9 = 0.0f;
            if (full) {
                float2 pe = ((const float2*)(pb + 8))[0];
                float2 te = ((const float2*)(tb + 8))[0];
                px8 = pe.x; px9 = pe.y; tx8 = te.x; tx9 = te.y;
            }
        }

        acc += wpair(p0.x, p0.y, p0.z,  t0.x, t0.y, t0.z);
        acc += wpair(p0.y, p0.z, p0.w,  t0.y, t0.z, t0.w);
        acc += wpair(p0.z, p0.w, p1.x,  t0.z, t0.w, t1.x);
        acc += wpair(p0.w, p1.x, p1.y,  t0.w, t1.x, t1.y);
        acc += wpair(p1.x, p1.y, p1.z,  t1.x, t1.y, t1.z);
        acc += wpair(p1.y, p1.z, p1.w,  t1.y, t1.z, t1.w);
        if (full) {
            acc += wpair(p1.z, p1.w, px8,  t1.z, t1.w, tx8);
            acc += wpair(p1.w, px8, px9,   t1.w, tx8, tx9);
        }
    }

    // Deterministic intra-block reduction.
    #pragma unroll
    for (int o = 16; o > 0; o >>= 1)
        acc += __shfl_down_sync(0xffffffffu, acc, o);

    __shared__ float red[NTHREADS / 32];
    int warp = threadIdx.x >> 5;
    if (lane == 0) red[warp] = acc;
    __syncthreads();

    __shared__ bool is_last;
    if (threadIdx.x == 0) {
        float v = 0.0f;
        #pragma unroll
        for (int w = 0; w < NTHREADS / 32; ++w) v += red[w];
        g_partials[blockIdx.x] = v;
        __threadfence();
        unsigned int old = atomicAdd(&g_counter, 1u);
        is_last = ((old + 1u) % (unsigned)NBLOCKS) == 0u;
    }
    __syncthreads();

    if (!is_last) return;

    // Last-arriving block: deterministic final reduction over 1024 partials.
    __shared__ double sh[NTHREADS];
    double s = 0.0;
    for (int i = threadIdx.x; i < NBLOCKS; i += NTHREADS)
        s += (double)g_partials[i];
    sh[threadIdx.x] = s;
    __syncthreads();
    #pragma unroll
    for (int stride = NTHREADS / 2; stride > 0; stride >>= 1) {
        if (threadIdx.x < stride) sh[threadIdx.x] += sh[threadIdx.x + stride];
        __syncthreads();
    }
    if (threadIdx.x == 0)
        out[0] = (float)(sh[0] / ((double)B_ROWS * (double)L_OUT));
}

extern "C" void kernel_launch(void* const* d_in, const int* in_sizes, int n_in,
                              void* d_out, int out_size) {
    const float* pred = (const float*)d_in[0];
    const float* targ = (const float*)d_in[1];
    vol_loss_fused<<<NBLOCKS, NTHREADS>>>(pred, targ, (float*)d_out);
}